// round 10
// baseline (speedup 1.0000x reference)
#include <cuda_runtime.h>
#include <cuda_fp16.h>
#include <cstdint>

// Problem constants
#define B_    256
#define T_    128
#define NIN   1156
#define NHID  1024
#define NOUT  10
#define M_    (T_ * B_)
#define BETA  0.95f
#define THR   1.0f
#define NINP  1184                 // NIN padded to 37*32 (zero-filled)
#define K4    (NINP / 4)           // 296 float4-groups per row

// Scratch
__device__ float    g_cur[(size_t)M_ * NHID];            // [T, B, H] 128 MiB
__device__ unsigned g_spk[(size_t)M_ * NHID / 32];       // packed spikes
__device__ float    g_y  [(size_t)M_ * NOUT];
__device__ __half   g_xhi[(size_t)M_ * NINP];            // 77.6 MiB
__device__ __half   g_xlo[(size_t)M_ * NINP];
__device__ __half   g_whi[(size_t)NHID * NINP];          // 2.4 MiB
__device__ __half   g_wlo[(size_t)NHID * NINP];

// ---------------------------------------------------------------------------
// fp16 hi/lo split: v = hi + lo/2048 (lo scaled into normal range)
// ---------------------------------------------------------------------------
__device__ __forceinline__ void split_pack(float v0, float v1,
                                           uint32_t& hi, uint32_t& lo) {
    __half h0 = __float2half_rn(v0);
    __half h1 = __float2half_rn(v1);
    __half l0 = __float2half_rn((v0 - __half2float(h0)) * 2048.f);
    __half l1 = __float2half_rn((v1 - __half2float(h1)) * 2048.f);
    __half2 hp = __halves2half2(h0, h1);
    __half2 lp = __halves2half2(l0, l1);
    hi = *reinterpret_cast<uint32_t*>(&hp);
    lo = *reinterpret_cast<uint32_t*>(&lp);
}

// Pre-pass: X [B,T,NIN] fp32 -> g_xhi/g_xlo [m, NINP] fp16, m = t*256+b
__global__ __launch_bounds__(256)
void split_x_kernel(const float* __restrict__ x)
{
    const int idx = blockIdx.x * blockDim.x + threadIdx.x;  // over M_*K4
    const int m  = idx / K4;
    const int k4 = idx - m * K4;
    const int k  = k4 * 4;
    const int t  = m >> 8;
    const int b  = m & 255;
    float4 v = make_float4(0.f, 0.f, 0.f, 0.f);
    if (k < NIN)  // NIN % 4 == 0: chunk fully valid or fully OOB
        v = *reinterpret_cast<const float4*>(x + ((size_t)b * T_ + t) * NIN + k);
    uint2 hi, lo;
    split_pack(v.x, v.y, hi.x, lo.x);
    split_pack(v.z, v.w, hi.y, lo.y);
    const size_t o = (size_t)m * NINP + k;
    *reinterpret_cast<uint2*>(&g_xhi[o]) = hi;
    *reinterpret_cast<uint2*>(&g_xlo[o]) = lo;
}

// Pre-pass: W1 [NHID,NIN] fp32 * 1024 -> g_whi/g_wlo [h, NINP] fp16
__global__ __launch_bounds__(256)
void split_w_kernel(const float* __restrict__ W1)
{
    const int idx = blockIdx.x * blockDim.x + threadIdx.x;  // over NHID*K4
    if (idx >= NHID * K4) return;
    const int h  = idx / K4;
    const int k4 = idx - h * K4;
    const int k  = k4 * 4;
    float4 v = make_float4(0.f, 0.f, 0.f, 0.f);
    if (k < NIN)
        v = *reinterpret_cast<const float4*>(W1 + (size_t)h * NIN + k);
    uint2 hi, lo;
    split_pack(v.x * 1024.f, v.y * 1024.f, hi.x, lo.x);
    split_pack(v.z * 1024.f, v.w * 1024.f, hi.y, lo.y);
    const size_t o = (size_t)h * NINP + k;
    *reinterpret_cast<uint2*>(&g_whi[o]) = hi;
    *reinterpret_cast<uint2*>(&g_wlo[o]) = lo;
}

// ---------------------------------------------------------------------------
// GEMM1: CUR[m,h] = sum_k X[m,k]*W1[h,k] via pre-split fp16 hi/lo operands.
// cur1 = (SUM_hh + SUM_c/2048)/1024, c = a_hi*w_lo + a_lo*w_hi.
// Chunk-local mma accumulators, RN drain. cp.async 3-stage pipeline.
// CTA 128x128, k-chunk 32.
// ---------------------------------------------------------------------------
#define KCH      37
#define ROWB     80                // bytes per smem row (32 fp16 + 8 pad)
#define TILE_SB  (128 * ROWB)      // 10240 B
#define OFF_AHI  0
#define OFF_ALO  (TILE_SB)
#define OFF_BHI  (2 * TILE_SB)
#define OFF_BLO  (3 * TILE_SB)
#define STAGE_SB (4 * TILE_SB)     // 40960 B
#define NSTAGE   3
#define SMEM_DYN (NSTAGE * STAGE_SB)  // 122880 B

__device__ __forceinline__ void cpa16(uint32_t dst, const void* src) {
    asm volatile("cp.async.cg.shared.global [%0], [%1], 16;"
                 :: "r"(dst), "l"(src) : "memory");
}
#define CPA_COMMIT() asm volatile("cp.async.commit_group;" ::: "memory")
#define CPA_WAIT(n)  asm volatile("cp.async.wait_group %0;" :: "n"(n) : "memory")

__device__ __forceinline__ void ldm_x4(uint32_t addr, uint32_t& r0, uint32_t& r1,
                                       uint32_t& r2, uint32_t& r3) {
    asm volatile("ldmatrix.sync.aligned.m8n8.x4.shared.b16 {%0,%1,%2,%3}, [%4];"
                 : "=r"(r0), "=r"(r1), "=r"(r2), "=r"(r3) : "r"(addr));
}

__device__ __forceinline__ void mma_f16(float* c, const uint32_t* a, const uint32_t* b) {
    asm volatile(
        "mma.sync.aligned.m16n8k16.row.col.f32.f16.f16.f32 "
        "{%0,%1,%2,%3}, {%4,%5,%6,%7}, {%8,%9}, {%0,%1,%2,%3};"
        : "+f"(c[0]), "+f"(c[1]), "+f"(c[2]), "+f"(c[3])
        : "r"(a[0]), "r"(a[1]), "r"(a[2]), "r"(a[3]), "r"(b[0]), "r"(b[1]));
}

__global__ __launch_bounds__(256, 1)
void gemm1_mma_kernel()
{
    extern __shared__ char smem[];
    uint32_t sbase;
    asm("{ .reg .u64 t; cvta.to.shared.u64 t, %1; cvt.u32.u64 %0, t; }"
        : "=r"(sbase) : "l"(smem));

    const int tid   = threadIdx.x;
    const int lane  = tid & 31;
    const int w     = tid >> 5;
    const int mtile = blockIdx.y;     // 0..255
    const int ntile = blockIdx.x;     // 0..7
    const int MW    = (w & 1) * 64;
    const int NW    = (w >> 1) * 32;
    const int m0    = mtile * 128;
    const int n0    = ntile * 128;

    // cp.async plan: 8 x 16B per thread per chunk (2048 chunks/stage)
    const __half* srcs[8];
    uint32_t doff[8];
#pragma unroll
    for (int i = 0; i < 8; i++) {
        const int idx  = i * 256 + tid;      // 0..2047
        const int tile = idx >> 9;           // 0..3
        const int r    = (idx >> 2) & 127;
        const int c4   = idx & 3;
        const __half* base =
            (tile == 0) ? g_xhi + (size_t)(m0 + r) * NINP :
            (tile == 1) ? g_xlo + (size_t)(m0 + r) * NINP :
            (tile == 2) ? g_whi + (size_t)(n0 + r) * NINP :
                          g_wlo + (size_t)(n0 + r) * NINP;
        srcs[i] = base + c4 * 8;
        doff[i] = (uint32_t)(tile * TILE_SB + r * ROWB + c4 * 16);
    }

    float acc[4][4][4];
#pragma unroll
    for (int mi = 0; mi < 4; mi++)
#pragma unroll
        for (int nj = 0; nj < 4; nj++)
#pragma unroll
            for (int q = 0; q < 4; q++) acc[mi][nj][q] = 0.f;

    // ldmatrix lane addressing
    const int sub = lane >> 3;
    const int l7  = lane & 7;
    const int a_r = MW + (sub & 1) * 8 + l7;
    const int a_c = (sub >> 1) * 8;
    const int b_r = NW + (sub >> 1) * 8 + l7;
    const int b_c = (sub & 1) * 8;

    auto issue = [&](int c) {
        const uint32_t sb = sbase + (uint32_t)(c % NSTAGE) * STAGE_SB;
        const int k0 = c * 32;
#pragma unroll
        for (int i = 0; i < 8; i++)
            cpa16(sb + doff[i], srcs[i] + k0);
        CPA_COMMIT();
    };

    // prologue: fill 3 stages
    issue(0); issue(1); issue(2);

    for (int c = 0; c < KCH; c++) {
        CPA_WAIT(2);            // chunk c's group complete
        __syncthreads();

        const uint32_t stg = sbase + (uint32_t)(c % NSTAGE) * STAGE_SB;
#pragma unroll
        for (int mh = 0; mh < 4; mh++) {
            float accT[2][4][4];
#pragma unroll
            for (int g = 0; g < 2; g++)
#pragma unroll
                for (int nj = 0; nj < 4; nj++)
#pragma unroll
                    for (int q = 0; q < 4; q++) accT[g][nj][q] = 0.f;

#pragma unroll
            for (int ks = 0; ks < 2; ks++) {
                uint32_t ah[4], al[4], bh[4][2], bl[4][2];
                const uint32_t ao = stg +
                    (uint32_t)((a_r + mh * 16) * ROWB + (ks * 16 + a_c) * 2);
                ldm_x4(ao + OFF_AHI, ah[0], ah[1], ah[2], ah[3]);
                ldm_x4(ao + OFF_ALO, al[0], al[1], al[2], al[3]);
#pragma unroll
                for (int nt = 0; nt < 2; nt++) {
                    const uint32_t bo = stg +
                        (uint32_t)((b_r + nt * 16) * ROWB + (ks * 16 + b_c) * 2);
                    uint32_t r0, r1, r2, r3;
                    ldm_x4(bo + OFF_BHI, r0, r1, r2, r3);
                    bh[nt * 2][0] = r0; bh[nt * 2][1] = r1;
                    bh[nt * 2 + 1][0] = r2; bh[nt * 2 + 1][1] = r3;
                    ldm_x4(bo + OFF_BLO, r0, r1, r2, r3);
                    bl[nt * 2][0] = r0; bl[nt * 2][1] = r1;
                    bl[nt * 2 + 1][0] = r2; bl[nt * 2 + 1][1] = r3;
                }
#pragma unroll
                for (int nj = 0; nj < 4; nj++) {
                    mma_f16(accT[0][nj], ah, bh[nj]);
                    mma_f16(accT[1][nj], ah, bl[nj]);
                    mma_f16(accT[1][nj], al, bh[nj]);
                }
            }
#pragma unroll
            for (int nj = 0; nj < 4; nj++)
#pragma unroll
                for (int q = 0; q < 4; q++)
                    acc[mh][nj][q] += accT[0][nj][q]
                                    + accT[1][nj][q] * (1.f / 2048.f);
        }

        __syncthreads();        // all warps done reading stage c%3
        if (c + 3 < KCH) issue(c + 3);
    }

    // epilogue: undo W scale
    const int mbase = m0 + MW + (lane >> 2);
    const int nbase = n0 + NW + (lane & 3) * 2;
    const float S = 1.f / 1024.f;
#pragma unroll
    for (int mi = 0; mi < 4; mi++)
#pragma unroll
        for (int nj = 0; nj < 4; nj++) {
            const int r = mbase + mi * 16;
            const int col = nbase + nj * 8;
            *reinterpret_cast<float2*>(&g_cur[(size_t)r * NHID + col]) =
                make_float2(acc[mi][nj][0] * S, acc[mi][nj][1] * S);
            *reinterpret_cast<float2*>(&g_cur[(size_t)(r + 8) * NHID + col]) =
                make_float2(acc[mi][nj][2] * S, acc[mi][nj][3] * S);
        }
}

// ---------------------------------------------------------------------------
// Kernel 2: per-(b,h) LIF scan; packed spike bits via ballot.
// ---------------------------------------------------------------------------
__global__ __launch_bounds__(256)
void spike_scan_kernel()
{
    const int tid  = blockIdx.x * blockDim.x + threadIdx.x;
    const int BH   = B_ * NHID;
    const int widx = tid >> 5;
    float mem1 = 0.f;

    for (int t = 0; t < T_; t++) {
        const float c = g_cur[(size_t)t * BH + tid];
        const float reset = (mem1 > THR) ? THR : 0.f;
        mem1 = BETA * mem1 + c - reset;
        const unsigned bal = __ballot_sync(0xffffffffu, (mem1 - THR) > 0.f);
        if ((tid & 31) == 0)
            g_spk[(size_t)t * (BH / 32) + widx] = bal;
    }
}

// ---------------------------------------------------------------------------
// Kernel 3: Y[t,b,o] = sum_h spk[t,b,h] * W2[o,h]
// ---------------------------------------------------------------------------
__global__ __launch_bounds__(256)
void ygemm_kernel(const float* __restrict__ W2)
{
    __shared__ float w2s[NOUT * NHID];
    for (int i = threadIdx.x; i < NOUT * NHID; i += blockDim.x)
        w2s[i] = W2[i];
    __syncthreads();

    const int row = blockIdx.x * blockDim.x + threadIdx.x;
    float acc[NOUT];
#pragma unroll
    for (int o = 0; o < NOUT; o++) acc[o] = 0.f;

    const unsigned* sp = g_spk + (size_t)row * (NHID / 32);
#pragma unroll 4
    for (int wd = 0; wd < NHID / 32; wd++) {
        unsigned bits = sp[wd];
        while (bits) {
            const int j = __ffs(bits) - 1;
            bits &= bits - 1;
            const int h = (wd << 5) + j;
#pragma unroll
            for (int o = 0; o < NOUT; o++)
                acc[o] += w2s[o * NHID + h];
        }
    }

    float* yp = g_y + (size_t)row * NOUT;
#pragma unroll
    for (int o = 0; o < NOUT; o++) yp[o] = acc[o];
}

// ---------------------------------------------------------------------------
// Kernel 4: mem2 leaky scan, write output [T, B, NOUT]
// ---------------------------------------------------------------------------
__global__ __launch_bounds__(256)
void out_scan_kernel(float* __restrict__ out)
{
    const int idx = blockIdx.x * blockDim.x + threadIdx.x;
    if (idx >= B_ * NOUT) return;
    const int BO = B_ * NOUT;
    float mem2 = 0.f;
#pragma unroll
    for (int tb = 0; tb < T_; tb += 16) {
        float v[16];
#pragma unroll
        for (int u = 0; u < 16; u++)
            v[u] = g_y[(size_t)(tb + u) * BO + idx];
#pragma unroll
        for (int u = 0; u < 16; u++) {
            mem2 = BETA * mem2 + v[u];
            out[(size_t)(tb + u) * BO + idx] = mem2;
        }
    }
}

// ---------------------------------------------------------------------------
extern "C" void kernel_launch(void* const* d_in, const int* in_sizes, int n_in,
                              void* d_out, int out_size)
{
    const float* x  = (const float*)d_in[0];   // [B, T, NIN]
    const float* W1 = (const float*)d_in[1];   // [NHID, NIN]
    const float* W2 = (const float*)d_in[2];   // [NOUT, NHID]
    float* out = (float*)d_out;                // [T, B, NOUT]

    cudaFuncSetAttribute(gemm1_mma_kernel,
                         cudaFuncAttributeMaxDynamicSharedMemorySize, SMEM_DYN);

    split_x_kernel<<<(M_ * K4) / 256, 256>>>(x);
    split_w_kernel<<<(NHID * K4 + 255) / 256, 256>>>(W1);

    dim3 grid1(NHID / 128, M_ / 128);          // (8, 256)
    gemm1_mma_kernel<<<grid1, 256, SMEM_DYN>>>();

    spike_scan_kernel<<<(B_ * NHID) / 256, 256>>>();

    ygemm_kernel<<<M_ / 256, 256>>>(W2);

    out_scan_kernel<<<(B_ * NOUT + 255) / 256, 256>>>(out);
}